// round 1
// baseline (speedup 1.0000x reference)
#include <cuda_runtime.h>

#define BATCH 8192
#define IN_F  1024
#define OUT_F 1024
#define NB    8      // basis functions per input (GRID + K)
#define NK    12     // extended knot count (GRID + 2K + 1)

#define BM  128      // batch tile
#define BN  128      // out tile
#define BKI 4        // input features per stage
#define KD  (BKI * 9)  // expanded K-depth per stage = 36

__device__ __forceinline__ void fma2(unsigned long long &d,
                                     unsigned long long a,
                                     unsigned long long b) {
    asm volatile("fma.rn.f32x2 %0, %1, %2, %0;" : "+l"(d) : "l"(a), "l"(b));
}

__device__ __forceinline__ unsigned long long pack2(float lo, float hi) {
    unsigned long long r;
    asm("mov.b64 %0, {%1, %2};" : "=l"(r) : "f"(lo), "f"(hi));
    return r;
}

__global__ __launch_bounds__(256)
void kan_fused_kernel(const float* __restrict__ x,     // (BATCH, IN_F)
                      const float* __restrict__ bw,    // (OUT_F, IN_F)
                      const float* __restrict__ sw,    // (OUT_F, IN_F, 8)
                      const float* __restrict__ grid,  // (IN_F, 12) rows identical
                      float* __restrict__ out)         // (BATCH, OUT_F)
{
    __shared__ float Fs[KD][BM];   // expanded features: row i*9+0 = x, +1..8 = basis
    __shared__ float Ws[KD][BN];   // expanded weights:  row i*9+0 = base, +1..8 = spline
    __shared__ float s_kn[NK];
    __shared__ float s_rL[30];
    __shared__ float s_rR[30];

    const int tid = threadIdx.x;
    const int bm0 = blockIdx.y * BM;
    const int on0 = blockIdx.x * BN;

    // --- knot vector + reciprocal denominator tables (uniform across i, use row 0)
    if (tid < NK) s_kn[tid] = grid[tid];
    __syncthreads();
    if (tid < 30) {
        int p = tid / 10 + 1;   // degree 1..3
        int j = tid % 10;
        if (j <= 10 - p) {
            s_rL[tid] = 1.0f / (s_kn[j + p]     - s_kn[j]);
            s_rR[tid] = 1.0f / (s_kn[j + p + 1] - s_kn[j + 1]);
        } else {
            s_rL[tid] = 0.0f;
            s_rR[tid] = 0.0f;
        }
    }

    const int ty = tid >> 4;     // 0..15 -> M micro-tile
    const int tx = tid & 15;     // 0..15 -> N micro-tile

    unsigned long long acc[8][4];
#pragma unroll
    for (int m = 0; m < 8; m++)
#pragma unroll
        for (int n = 0; n < 4; n++) acc[m][n] = 0ull;

    const int  o_local = tid & 127;
    const int  part    = tid >> 7;            // 0 or 1
    const long o       = (long)on0 + o_local;

    for (int i0 = 0; i0 < IN_F; i0 += BKI) {
        __syncthreads();

        // ---------------- load expanded weight tile ----------------
        if (part == 0) {
#pragma unroll
            for (int ii = 0; ii < 2; ii++) {
                const float4* sp = (const float4*)(sw + ((o * IN_F + (i0 + ii)) << 3));
                float4 s0 = sp[0];
                float4 s1 = sp[1];
                Ws[ii*9 + 1][o_local] = s0.x;  Ws[ii*9 + 2][o_local] = s0.y;
                Ws[ii*9 + 3][o_local] = s0.z;  Ws[ii*9 + 4][o_local] = s0.w;
                Ws[ii*9 + 5][o_local] = s1.x;  Ws[ii*9 + 6][o_local] = s1.y;
                Ws[ii*9 + 7][o_local] = s1.z;  Ws[ii*9 + 8][o_local] = s1.w;
            }
        } else {
#pragma unroll
            for (int ii = 2; ii < 4; ii++) {
                const float4* sp = (const float4*)(sw + ((o * IN_F + (i0 + ii)) << 3));
                float4 s0 = sp[0];
                float4 s1 = sp[1];
                Ws[ii*9 + 1][o_local] = s0.x;  Ws[ii*9 + 2][o_local] = s0.y;
                Ws[ii*9 + 3][o_local] = s0.z;  Ws[ii*9 + 4][o_local] = s0.w;
                Ws[ii*9 + 5][o_local] = s1.x;  Ws[ii*9 + 6][o_local] = s1.y;
                Ws[ii*9 + 7][o_local] = s1.z;  Ws[ii*9 + 8][o_local] = s1.w;
            }
            float4 bv = *(const float4*)(bw + o * IN_F + i0);
            Ws[ 0][o_local] = bv.x;
            Ws[ 9][o_local] = bv.y;
            Ws[18][o_local] = bv.z;
            Ws[27][o_local] = bv.w;
        }

        // ---------------- load x tile + expand B-spline basis ----------------
#pragma unroll
        for (int r = 0; r < 2; r++) {
            int idx = tid + r * 256;        // 0..511
            int bl  = idx & 127;            // batch within tile
            int il  = idx >> 7;             // input feature within chunk (0..3)
            float xv = x[(long)(bm0 + bl) * IN_F + (i0 + il)];

            float b[11];
#pragma unroll
            for (int j = 0; j < 11; j++)
                b[j] = (xv >= s_kn[j] && xv < s_kn[j + 1]) ? 1.0f : 0.0f;
#pragma unroll
            for (int p = 1; p <= 3; p++) {
#pragma unroll
                for (int j = 0; j <= 10 - p; j++) {
                    b[j] = (xv - s_kn[j])         * s_rL[(p - 1) * 10 + j] * b[j]
                         + (s_kn[j + p + 1] - xv) * s_rR[(p - 1) * 10 + j] * b[j + 1];
                }
            }
            Fs[il * 9 + 0][bl] = xv;
#pragma unroll
            for (int c = 0; c < NB; c++)
                Fs[il * 9 + 1 + c][bl] = b[c];
        }

        __syncthreads();

        // ---------------- 128x128x36 FMA stage (f32x2 packed) ----------------
#pragma unroll
        for (int k = 0; k < KD; k++) {
            float4 a0 = *(const float4*)&Fs[k][ty * 8];
            float4 a1 = *(const float4*)&Fs[k][ty * 8 + 4];
            float4 b0 = *(const float4*)&Ws[k][tx * 8];
            float4 b1 = *(const float4*)&Ws[k][tx * 8 + 4];

            unsigned long long bb[4];
            bb[0] = pack2(b0.x, b0.y);
            bb[1] = pack2(b0.z, b0.w);
            bb[2] = pack2(b1.x, b1.y);
            bb[3] = pack2(b1.z, b1.w);

            float av[8] = {a0.x, a0.y, a0.z, a0.w, a1.x, a1.y, a1.z, a1.w};
#pragma unroll
            for (int m = 0; m < 8; m++) {
                unsigned long long aa = pack2(av[m], av[m]);
#pragma unroll
                for (int n = 0; n < 4; n++)
                    fma2(acc[m][n], aa, bb[n]);
            }
        }
    }

    // ---------------- epilogue ----------------
#pragma unroll
    for (int m = 0; m < 8; m++) {
        long row = (long)bm0 + ty * 8 + m;
        float* op = out + row * OUT_F + on0 + tx * 8;
#pragma unroll
        for (int n = 0; n < 4; n++) {
            float2 v = *(float2*)&acc[m][n];
            *(float2*)(op + 2 * n) = v;
        }
    }
}

extern "C" void kernel_launch(void* const* d_in, const int* in_sizes, int n_in,
                              void* d_out, int out_size) {
    const float* x  = (const float*)d_in[0];   // (8192, 1024)
    const float* bw = (const float*)d_in[1];   // (1024, 1024)
    const float* sw = (const float*)d_in[2];   // (1024, 1024, 8)
    const float* gr = (const float*)d_in[3];   // (1024, 12)
    float* out = (float*)d_out;                // (8192, 1024)

    dim3 grid(OUT_F / BN, BATCH / BM);         // (8, 64)
    dim3 block(256);
    kan_fused_kernel<<<grid, block>>>(x, bw, sw, gr, out);
}

// round 2
// speedup vs baseline: 1.0005x; 1.0005x over previous
#include <cuda_runtime.h>

#define BATCH 8192
#define IN_F  1024
#define OUT_F 1024
#define NB    8      // basis functions per input (GRID + K)
#define NK    12     // extended knot count (GRID + 2K + 1)

#define BM  128      // batch tile
#define BN  128      // out tile
#define BKI 4        // input features per stage
#define KD  (BKI * 9)  // expanded K-depth per stage = 36

__device__ __forceinline__ void fma2(unsigned long long &d,
                                     unsigned long long a,
                                     unsigned long long b) {
    asm volatile("fma.rn.f32x2 %0, %1, %2, %0;" : "+l"(d) : "l"(a), "l"(b));
}

__device__ __forceinline__ unsigned long long pack2(float lo, float hi) {
    unsigned long long r;
    asm("mov.b64 %0, {%1, %2};" : "=l"(r) : "f"(lo), "f"(hi));
    return r;
}

__global__ __launch_bounds__(256)
void kan_fused_kernel(const float* __restrict__ x,     // (BATCH, IN_F)
                      const float* __restrict__ bw,    // (OUT_F, IN_F)
                      const float* __restrict__ sw,    // (OUT_F, IN_F, 8)
                      const float* __restrict__ grid,  // (IN_F, 12) rows identical
                      float* __restrict__ out)         // (BATCH, OUT_F)
{
    __shared__ float Fs[KD][BM];   // expanded features: row i*9+0 = x, +1..8 = basis
    __shared__ float Ws[KD][BN];   // expanded weights:  row i*9+0 = base, +1..8 = spline
    __shared__ float s_kn[NK];
    __shared__ float s_rL[30];
    __shared__ float s_rR[30];

    const int tid = threadIdx.x;
    const int bm0 = blockIdx.y * BM;
    const int on0 = blockIdx.x * BN;

    // --- knot vector + reciprocal denominator tables (uniform across i, use row 0)
    if (tid < NK) s_kn[tid] = grid[tid];
    __syncthreads();
    if (tid < 30) {
        int p = tid / 10 + 1;   // degree 1..3
        int j = tid % 10;
        if (j <= 10 - p) {
            s_rL[tid] = 1.0f / (s_kn[j + p]     - s_kn[j]);
            s_rR[tid] = 1.0f / (s_kn[j + p + 1] - s_kn[j + 1]);
        } else {
            s_rL[tid] = 0.0f;
            s_rR[tid] = 0.0f;
        }
    }

    const int ty = tid >> 4;     // 0..15 -> M micro-tile
    const int tx = tid & 15;     // 0..15 -> N micro-tile

    unsigned long long acc[8][4];
#pragma unroll
    for (int m = 0; m < 8; m++)
#pragma unroll
        for (int n = 0; n < 4; n++) acc[m][n] = 0ull;

    const int  o_local = tid & 127;
    const int  part    = tid >> 7;            // 0 or 1
    const long o       = (long)on0 + o_local;

    for (int i0 = 0; i0 < IN_F; i0 += BKI) {
        __syncthreads();

        // ---------------- load expanded weight tile ----------------
        if (part == 0) {
#pragma unroll
            for (int ii = 0; ii < 2; ii++) {
                const float4* sp = (const float4*)(sw + ((o * IN_F + (i0 + ii)) << 3));
                float4 s0 = sp[0];
                float4 s1 = sp[1];
                Ws[ii*9 + 1][o_local] = s0.x;  Ws[ii*9 + 2][o_local] = s0.y;
                Ws[ii*9 + 3][o_local] = s0.z;  Ws[ii*9 + 4][o_local] = s0.w;
                Ws[ii*9 + 5][o_local] = s1.x;  Ws[ii*9 + 6][o_local] = s1.y;
                Ws[ii*9 + 7][o_local] = s1.z;  Ws[ii*9 + 8][o_local] = s1.w;
            }
        } else {
#pragma unroll
            for (int ii = 2; ii < 4; ii++) {
                const float4* sp = (const float4*)(sw + ((o * IN_F + (i0 + ii)) << 3));
                float4 s0 = sp[0];
                float4 s1 = sp[1];
                Ws[ii*9 + 1][o_local] = s0.x;  Ws[ii*9 + 2][o_local] = s0.y;
                Ws[ii*9 + 3][o_local] = s0.z;  Ws[ii*9 + 4][o_local] = s0.w;
                Ws[ii*9 + 5][o_local] = s1.x;  Ws[ii*9 + 6][o_local] = s1.y;
                Ws[ii*9 + 7][o_local] = s1.z;  Ws[ii*9 + 8][o_local] = s1.w;
            }
            float4 bv = *(const float4*)(bw + o * IN_F + i0);
            Ws[ 0][o_local] = bv.x;
            Ws[ 9][o_local] = bv.y;
            Ws[18][o_local] = bv.z;
            Ws[27][o_local] = bv.w;
        }

        // ---------------- load x tile + expand B-spline basis ----------------
#pragma unroll
        for (int r = 0; r < 2; r++) {
            int idx = tid + r * 256;        // 0..511
            int bl  = idx & 127;            // batch within tile
            int il  = idx >> 7;             // input feature within chunk (0..3)
            float xv = x[(long)(bm0 + bl) * IN_F + (i0 + il)];

            float b[11];
#pragma unroll
            for (int j = 0; j < 11; j++)
                b[j] = (xv >= s_kn[j] && xv < s_kn[j + 1]) ? 1.0f : 0.0f;
#pragma unroll
            for (int p = 1; p <= 3; p++) {
#pragma unroll
                for (int j = 0; j <= 10 - p; j++) {
                    b[j] = (xv - s_kn[j])         * s_rL[(p - 1) * 10 + j] * b[j]
                         + (s_kn[j + p + 1] - xv) * s_rR[(p - 1) * 10 + j] * b[j + 1];
                }
            }
            Fs[il * 9 + 0][bl] = xv;
#pragma unroll
            for (int c = 0; c < NB; c++)
                Fs[il * 9 + 1 + c][bl] = b[c];
        }

        __syncthreads();

        // ---------------- 128x128x36 FMA stage (f32x2 packed) ----------------
#pragma unroll
        for (int k = 0; k < KD; k++) {
            float4 a0 = *(const float4*)&Fs[k][ty * 8];
            float4 a1 = *(const float4*)&Fs[k][ty * 8 + 4];
            float4 b0 = *(const float4*)&Ws[k][tx * 8];
            float4 b1 = *(const float4*)&Ws[k][tx * 8 + 4];

            unsigned long long bb[4];
            bb[0] = pack2(b0.x, b0.y);
            bb[1] = pack2(b0.z, b0.w);
            bb[2] = pack2(b1.x, b1.y);
            bb[3] = pack2(b1.z, b1.w);

            float av[8] = {a0.x, a0.y, a0.z, a0.w, a1.x, a1.y, a1.z, a1.w};
#pragma unroll
            for (int m = 0; m < 8; m++) {
                unsigned long long aa = pack2(av[m], av[m]);
#pragma unroll
                for (int n = 0; n < 4; n++)
                    fma2(acc[m][n], aa, bb[n]);
            }
        }
    }

    // ---------------- epilogue ----------------
#pragma unroll
    for (int m = 0; m < 8; m++) {
        long row = (long)bm0 + ty * 8 + m;
        float* op = out + row * OUT_F + on0 + tx * 8;
#pragma unroll
        for (int n = 0; n < 4; n++) {
            float2 v = *(float2*)&acc[m][n];
            *(float2*)(op + 2 * n) = v;
        }
    }
}

extern "C" void kernel_launch(void* const* d_in, const int* in_sizes, int n_in,
                              void* d_out, int out_size) {
    const float* x  = (const float*)d_in[0];   // (8192, 1024)
    const float* bw = (const float*)d_in[1];   // (1024, 1024)
    const float* sw = (const float*)d_in[2];   // (1024, 1024, 8)
    const float* gr = (const float*)d_in[3];   // (1024, 12)
    float* out = (float*)d_out;                // (8192, 1024)

    dim3 grid(OUT_F / BN, BATCH / BM);         // (8, 64)
    dim3 block(256);
    kan_fused_kernel<<<grid, block>>>(x, bw, sw, gr, out);
}